// round 3
// baseline (speedup 1.0000x reference)
#include <cuda_runtime.h>
#include <cuda_bf16.h>

// ---------------------------------------------------------------------------
// R3: R2 (320us) was dual-bottlenecked: MUFU pipe ~150us (4 MUFU/neuron-pair
// in flow tanh) co-equal with FMA pipe ~150us, and reg-capped at 16 warps/SM.
//  1. Occupancy 16 -> 24 warps: NC 20->16, S[] recomputed inline (frees 64 regs
//     worth of pressure), __launch_bounds__(256,3).
//  2. Pairwise-batched reciprocal in the flow tanh: 1 rcp per 2 neurons
//     (MUFU 4 -> 3 per neuron-pair).
//  3. Shooting integrations (which only set v, loose error budget) use a
//     12-term truncation of the Chebyshev row; final integrate uses all 16.
//  4. GL 2048 -> 1024, __cosf in precompute.
// ---------------------------------------------------------------------------

#define NC      16          // stored Chebyshev terms (final integrate)
#define NCS     12          // terms used during shooting integrations
#define GL      1024
#define C_MIN   (-1.0f)
#define C_MAX   (2.0f)
#define C_MID   (0.5f)
#define C_HALF  (1.5f)
#define C_INVH  (0.66666666666666667f)
#define C_MOFF  (-0.33333333333333333f)
#define PI_F    3.14159265358979323846f
#define FD_EPS_F 1e-4f

typedef unsigned long long u64;

__device__ float g_nodes[GL * NC];
__device__ float g_coef [GL * NC];

// packed f32x2 helpers ------------------------------------------------------
__device__ __forceinline__ u64 pk(float lo, float hi) {
    u64 r; asm("mov.b64 %0, {%1, %2};" : "=l"(r) : "f"(lo), "f"(hi)); return r;
}
__device__ __forceinline__ void upk(u64 a, float& x, float& y) {
    asm("mov.b64 {%0, %1}, %2;" : "=f"(x), "=f"(y) : "l"(a));
}
__device__ __forceinline__ u64 pfma(u64 a, u64 b, u64 c) {
    u64 d; asm("fma.rn.f32x2 %0, %1, %2, %3;" : "=l"(d) : "l"(a), "l"(b), "l"(c)); return d;
}
__device__ __forceinline__ u64 pmul(u64 a, u64 b) {
    u64 d; asm("mul.rn.f32x2 %0, %1, %2;" : "=l"(d) : "l"(a), "l"(b)); return d;
}
__device__ __forceinline__ u64 padd(u64 a, u64 b) {
    u64 d; asm("add.rn.f32x2 %0, %1, %2;" : "=l"(d) : "l"(a), "l"(b)); return d;
}
__device__ __forceinline__ float ex2f(float x) {
    float y; asm("ex2.approx.f32 %0, %1;" : "=f"(y) : "f"(x)); return y;
}
__device__ __forceinline__ float rcpf(float x) {
    float y; asm("rcp.approx.f32 %0, %1;" : "=f"(y) : "f"(x)); return y;
}

#define PK_M1   0xBF800000BF800000ULL   // (-1, -1)
#define PK_ONE  0x3F8000003F800000ULL   // ( 1,  1)
#define PK_DT   0x3DCCCCCD3DCCCCCDULL   // (0.1, 0.1)
#define PK_NDT  0xBDCCCCCDBDCCCCCDULL   // (-0.1, -0.1)

// ----------------------------- precompute ----------------------------------

__device__ __forceinline__ float metric_eval(
    float c, float lam,
    const float* __restrict__ mW1, const float* __restrict__ mb1,
    const float* __restrict__ mW2, const float* __restrict__ mb2,
    const float* __restrict__ mW3, const float* __restrict__ mb3)
{
    float h1[8];
#pragma unroll
    for (int j = 0; j < 8; j++)
        h1[j] = tanhf(fmaf(c, mW1[j], fmaf(lam, mW1[8 + j], mb1[j])));
    float h2[8];
#pragma unroll
    for (int j = 0; j < 8; j++) {
        float p = mb2[j];
#pragma unroll
        for (int k = 0; k < 8; k++) p = fmaf(h1[k], mW2[k * 8 + j], p);
        h2[j] = tanhf(p);
    }
    float o = mb3[0];
#pragma unroll
    for (int k = 0; k < 8; k++) o = fmaf(h2[k], mW3[k], o);
    float sp = (o > 20.0f) ? o : log1pf(expf(o));
    return sp + 1e-6f;
}

__global__ void gamma_nodes_kernel(
    const float* __restrict__ mW1, const float* __restrict__ mb1,
    const float* __restrict__ mW2, const float* __restrict__ mb2,
    const float* __restrict__ mW3, const float* __restrict__ mb3)
{
    int id = blockIdx.x * blockDim.x + threadIdx.x;
    if (id >= GL * NC) return;
    int l = id / NC;
    int k = id - l * NC;
    float lam = (float)l * (1.0f / (GL - 1));
    float th = (k + 0.5f) * (PI_F / NC);
    float c  = C_MID + C_HALF * __cosf(th);

    float g0 = metric_eval(c,            lam, mW1, mb1, mW2, mb2, mW3, mb3);
    float gp = metric_eval(c + FD_EPS_F, lam, mW1, mb1, mW2, mb2, mW3, mb3);
    float gm = metric_eval(c - FD_EPS_F, lam, mW1, mb1, mW2, mb2, mW3, mb3);
    float dg = (gp - gm) * (1.0f / (2.0f * FD_EPS_F));
    g_nodes[id] = 0.5f * dg / g0;
}

__global__ void dct_kernel()
{
    int id = blockIdx.x * blockDim.x + threadIdx.x;
    if (id >= GL * NC) return;
    int l = id / NC;
    int j = id - l * NC;
    float s = 0.0f;
    for (int k = 0; k < NC; k++)
        s += g_nodes[l * NC + k] * __cosf((PI_F / NC) * (float)j * ((float)k + 0.5f));
    s *= (j == 0) ? (1.0f / NC) : (2.0f / NC);
    g_coef[l * NC + j] = s;
}

// ----------------------------- main kernel ---------------------------------

template<int NT>
__device__ __forceinline__ u64 eval_gamma_t(const u64 co[NC], u64 C)
{
    float cx, cy; upk(C, cx, cy);
    cx = fminf(fmaxf(cx, C_MIN), C_MAX);
    cy = fminf(fmaxf(cy, C_MIN), C_MAX);
    u64 T = pk(fmaf(cx, (float)C_INVH, (float)C_MOFF),
               fmaf(cy, (float)C_INVH, (float)C_MOFF));
    u64 T2 = padd(T, T);
    u64 b1 = 0ull, b2 = 0ull;
#pragma unroll
    for (int j = NT - 1; j >= 1; j--) {
        u64 d = pfma(b2, PK_M1, co[j]);
        u64 b = pfma(T2, b1, d);
        b2 = b1; b1 = b;
    }
    u64 d0 = pfma(b2, PK_M1, co[0]);
    return pfma(T, b1, d0);
}

// 10 Euler steps, c/v only (shooting: truncated Chebyshev)
__device__ __forceinline__ u64 integrate_c(const u64 co[NC], u64 C0, u64 V0)
{
    u64 C = C0, V = V0;
#pragma unroll 1
    for (int s = 0; s < 10; s++) {
        u64 G   = eval_gamma_t<NCS>(co, C);
        u64 Cn  = pfma(V, PK_DT, C);
        u64 gv  = pmul(G, V);
        u64 gvv = pmul(gv, V);
        V = pfma(gvv, PK_NDT, V);
        C = Cn;
    }
    return C;
}

// reference iterations 2..10 in closed form (affine model of F)
__device__ __forceinline__ float shoot_tail(float v0, float v1,
                                            float F0, float F1, float ctg)
{
    float dv = v1 - v0;
    float b  = (F1 - F0) / dv;
    float r  = 1.0f - 0.5f * b;
    float vs = v1 + (ctg - F1) / b;
    float r2 = r * r, r4 = r2 * r2, r8 = r4 * r4, r9 = r8 * r;
    float v10 = fmaf(r9, v1 - vs, vs);
    return (fabsf(dv) > 1e-6f) ? v10 : v1;
}

__global__ __launch_bounds__(256, 3)
void geodesic_main_kernel(
    const float* __restrict__ c_src, const float* __restrict__ c_tgt,
    const float* __restrict__ lamv,  const float* __restrict__ A_src,
    const float* __restrict__ sW1,   const float* __restrict__ sb1,
    const float* __restrict__ sW2,   const float* __restrict__ sb2,
    float* __restrict__ out, int n)
{
    // broadcast weights (k = 2*log2(e) folded in)
    __shared__ u64 shA[16], shB[16], shD[16], shW2[16], shS1[16], shS0[16];
    __shared__ float shT2;

    const float KTH = 2.8853900817779268f;   // 2*log2(e)
    int t = threadIdx.x;
    if (t < 16) {
        int j = t;
        float a  = KTH * sW1[j];
        float b  = KTH * sW1[16 + j];
        float cw = KTH * sW1[32 + j];
        float dw = KTH * sW1[48 + j];
        float b1 = KTH * sb1[j];
        float w2 = sW2[j];
        shA[j]  = pk(a, a);
        shB[j]  = pk(b, b);
        shD[j]  = pk(dw, dw);
        shS1[j] = pk(cw, cw);
        shS0[j] = pk(b1, b1);
        shW2[j] = pk(-2.0f * w2, -2.0f * w2);
    } else if (t == 16) {
        float s = sb2[0];
        for (int j = 0; j < 16; j++) s += sW2[j];
        shT2 = s;
    }
    __syncthreads();

    int half = (n + 1) >> 1;
    int i = blockIdx.x * 256 + t;
    if (i >= half) return;
    int i2 = i + half;
    bool has2 = (i2 < n);
    int j2 = has2 ? i2 : i;

    float c0x = c_src[i],  c0y = c_src[j2];
    float ctx = c_tgt[i],  cty = c_tgt[j2];
    float lmx = lamv[i],   lmy = lamv[j2];
    float a0x = A_src[i],  a0y = A_src[j2];

    // --- lambda-lerp of Chebyshev rows, packed ---
    float yx = fminf(fmaxf(lmx * (float)(GL - 1), 0.0f), (float)(GL - 1));
    float yy = fminf(fmaxf(lmy * (float)(GL - 1), 0.0f), (float)(GL - 1));
    int lx = min((int)yx, GL - 2);
    int ly = min((int)yy, GL - 2);
    float fx = yx - (float)lx;
    float fy = yy - (float)ly;

    const float4* rx0 = (const float4*)(g_coef + lx * NC);
    const float4* rx1 = (const float4*)(g_coef + (lx + 1) * NC);
    const float4* ry0 = (const float4*)(g_coef + ly * NC);
    const float4* ry1 = (const float4*)(g_coef + (ly + 1) * NC);

    u64 co[NC];
#pragma unroll
    for (int q = 0; q < NC / 4; q++) {
        float4 ax = __ldg(rx0 + q), bx = __ldg(rx1 + q);
        float4 ay = __ldg(ry0 + q), by = __ldg(ry1 + q);
        co[4*q+0] = pk(fmaf(fx, bx.x - ax.x, ax.x), fmaf(fy, by.x - ay.x, ay.x));
        co[4*q+1] = pk(fmaf(fx, bx.y - ax.y, ax.y), fmaf(fy, by.y - ay.y, ay.y));
        co[4*q+2] = pk(fmaf(fx, bx.z - ax.z, ax.z), fmaf(fy, by.z - ay.z, ay.z));
        co[4*q+3] = pk(fmaf(fx, bx.w - ax.w, ax.w), fmaf(fy, by.w - ay.w, ay.w));
    }

    // --- shooting: 2 truncated integrations + affine closed-form tail ---
    u64 C0p = pk(c0x, c0y);
    float v0x = ctx - c0x, v0y = cty - c0y;
    u64 F0p = integrate_c(co, C0p, pk(v0x, v0y));

    float F0x, F0y; upk(F0p, F0x, F0y);
    float v1x = fmaf(-0.5f, F0x - ctx, v0x);
    float v1y = fmaf(-0.5f, F0y - cty, v0y);
    u64 F1p = integrate_c(co, C0p, pk(v1x, v1y));
    float F1x, F1y; upk(F1p, F1x, F1y);

    float vx = shoot_tail(v0x, v1x, F0x, F1x, ctx);
    float vy = shoot_tail(v0y, v1y, F0y, F1y, cty);

    // --- final integrate with spectral flow (full NC terms) ---
    u64 LAM = pk(lmx, lmy);
    u64 C = C0p, V = pk(vx, vy), A = pk(a0x, a0y);
    u64 T2p = pk(shT2, shT2);
#pragma unroll 1
    for (int s = 0; s < 10; s++) {
        u64 G = eval_gamma_t<NC>(co, C);
        u64 acc = T2p;
#pragma unroll
        for (int j = 0; j < 16; j += 2) {
            // neuron j
            u64 pre0 = pfma(LAM, shS1[j], shS0[j]);
            pre0 = pfma(C, shA[j], pre0);
            pre0 = pfma(V, shB[j], pre0);
            pre0 = pfma(A, shD[j], pre0);
            float p0x, p0y; upk(pre0, p0x, p0y);
            u64 D0 = padd(pk(ex2f(p0x), ex2f(p0y)), PK_ONE);
            // neuron j+1
            u64 pre1 = pfma(LAM, shS1[j+1], shS0[j+1]);
            pre1 = pfma(C, shA[j+1], pre1);
            pre1 = pfma(V, shB[j+1], pre1);
            pre1 = pfma(A, shD[j+1], pre1);
            float p1x, p1y; upk(pre1, p1x, p1y);
            u64 D1 = padd(pk(ex2f(p1x), ex2f(p1y)), PK_ONE);
            // one reciprocal serves both: R = 1/(D0*D1)
            u64 P = pmul(D0, D1);
            float qx, qy; upk(P, qx, qy);
            u64 R  = pk(rcpf(qx), rcpf(qy));
            u64 r0 = pmul(R, D1);
            u64 r1 = pmul(R, D0);
            acc = pfma(r0, shW2[j],   acc);
            acc = pfma(r1, shW2[j+1], acc);
        }
        u64 Cn  = pfma(V, PK_DT, C);
        u64 gv  = pmul(G, V);
        u64 gvv = pmul(gv, V);
        V = pfma(gvv, PK_NDT, V);
        A = pfma(acc, PK_DT, A);
        C = Cn;
    }

    float Ax, Ay; upk(A, Ax, Ay);
    out[i] = Ax;
    if (has2) out[i2] = Ay;
}

// ----------------------------- launcher ------------------------------------

extern "C" void kernel_launch(void* const* d_in, const int* in_sizes, int n_in,
                              void* d_out, int out_size)
{
    const float* c_src = (const float*)d_in[0];
    const float* c_tgt = (const float*)d_in[1];
    const float* lam   = (const float*)d_in[2];
    const float* A_src = (const float*)d_in[3];
    const float* mW1 = (const float*)d_in[4];
    const float* mb1 = (const float*)d_in[5];
    const float* mW2 = (const float*)d_in[6];
    const float* mb2 = (const float*)d_in[7];
    const float* mW3 = (const float*)d_in[8];
    const float* mb3 = (const float*)d_in[9];
    const float* sW1 = (const float*)d_in[10];
    const float* sb1 = (const float*)d_in[11];
    const float* sW2 = (const float*)d_in[12];
    const float* sb2 = (const float*)d_in[13];

    int n = in_sizes[0];
    const int TB = 256;

    int pre_blocks = (GL * NC + TB - 1) / TB;
    gamma_nodes_kernel<<<pre_blocks, TB>>>(mW1, mb1, mW2, mb2, mW3, mb3);
    dct_kernel<<<pre_blocks, TB>>>();

    int half = (n + 1) / 2;
    int blocks = (half + TB - 1) / TB;
    geodesic_main_kernel<<<blocks, TB>>>(c_src, c_tgt, lam, A_src,
                                         sW1, sb1, sW2, sb2,
                                         (float*)d_out, n);
}

// round 5
// speedup vs baseline: 1.7258x; 1.7258x over previous
#include <cuda_runtime.h>
#include <cuda_bf16.h>

// ---------------------------------------------------------------------------
// R5 == R4 (bench infra failed; kernel never ran). Rationale:
// R3 regressed (320 -> 450us) because __launch_bounds__(256,3) forced
// regs<=84 and spilled the hot loops to local memory. Revert to the R2 shape
// (no occupancy cap, per-thread S[] in registers) and keep only pressure-
// neutral work reductions:
//  * NC 20 -> 16 stored Chebyshev terms (frees 8 regs, err ~1e-5)
//  * even/odd Chebyshev split: T_{2k}(t)=T_k(u), T_{2k+1}(t)=t*V_k(u),
//    u=2t^2-1 -> two independent 8-term Clenshaw chains, half the dependency
//    latency per Gamma eval (R2's main exposed stall at 16 warps/SM)
//  * pairwise-batched reciprocal in flow tanh: MUFU 640 -> 480 per thread
//  * shooting uses 12-term truncation; everything f32x2-packed as in R2
// ---------------------------------------------------------------------------

#define NC      16
#define NCS     12
#define GL      1024
#define C_MIN   (-1.0f)
#define C_MAX   (2.0f)
#define C_MID   (0.5f)
#define C_HALF  (1.5f)
#define C_INVH  (0.66666666666666667f)
#define C_MOFF  (-0.33333333333333333f)
#define PI_F    3.14159265358979323846f
#define FD_EPS_F 1e-4f

typedef unsigned long long u64;

__device__ float g_nodes[GL * NC];
__device__ float g_coef [GL * NC];

// packed f32x2 helpers ------------------------------------------------------
__device__ __forceinline__ u64 pk(float lo, float hi) {
    u64 r; asm("mov.b64 %0, {%1, %2};" : "=l"(r) : "f"(lo), "f"(hi)); return r;
}
__device__ __forceinline__ void upk(u64 a, float& x, float& y) {
    asm("mov.b64 {%0, %1}, %2;" : "=f"(x), "=f"(y) : "l"(a));
}
__device__ __forceinline__ u64 pfma(u64 a, u64 b, u64 c) {
    u64 d; asm("fma.rn.f32x2 %0, %1, %2, %3;" : "=l"(d) : "l"(a), "l"(b), "l"(c)); return d;
}
__device__ __forceinline__ u64 pmul(u64 a, u64 b) {
    u64 d; asm("mul.rn.f32x2 %0, %1, %2;" : "=l"(d) : "l"(a), "l"(b)); return d;
}
__device__ __forceinline__ u64 padd(u64 a, u64 b) {
    u64 d; asm("add.rn.f32x2 %0, %1, %2;" : "=l"(d) : "l"(a), "l"(b)); return d;
}
__device__ __forceinline__ float ex2f(float x) {
    float y; asm("ex2.approx.f32 %0, %1;" : "=f"(y) : "f"(x)); return y;
}
__device__ __forceinline__ float rcpf(float x) {
    float y; asm("rcp.approx.f32 %0, %1;" : "=f"(y) : "f"(x)); return y;
}

#define PK_M1   0xBF800000BF800000ULL   // (-1, -1)
#define PK_ONE  0x3F8000003F800000ULL   // ( 1,  1)
#define PK_DT   0x3DCCCCCD3DCCCCCDULL   // (0.1, 0.1)
#define PK_NDT  0xBDCCCCCDBDCCCCCDULL   // (-0.1, -0.1)

// ----------------------------- precompute ----------------------------------

__device__ __forceinline__ float metric_eval(
    float c, float lam,
    const float* __restrict__ mW1, const float* __restrict__ mb1,
    const float* __restrict__ mW2, const float* __restrict__ mb2,
    const float* __restrict__ mW3, const float* __restrict__ mb3)
{
    float h1[8];
#pragma unroll
    for (int j = 0; j < 8; j++)
        h1[j] = tanhf(fmaf(c, mW1[j], fmaf(lam, mW1[8 + j], mb1[j])));
    float h2[8];
#pragma unroll
    for (int j = 0; j < 8; j++) {
        float p = mb2[j];
#pragma unroll
        for (int k = 0; k < 8; k++) p = fmaf(h1[k], mW2[k * 8 + j], p);
        h2[j] = tanhf(p);
    }
    float o = mb3[0];
#pragma unroll
    for (int k = 0; k < 8; k++) o = fmaf(h2[k], mW3[k], o);
    float sp = (o > 20.0f) ? o : log1pf(expf(o));
    return sp + 1e-6f;
}

__global__ void gamma_nodes_kernel(
    const float* __restrict__ mW1, const float* __restrict__ mb1,
    const float* __restrict__ mW2, const float* __restrict__ mb2,
    const float* __restrict__ mW3, const float* __restrict__ mb3)
{
    int id = blockIdx.x * blockDim.x + threadIdx.x;
    if (id >= GL * NC) return;
    int l = id / NC;
    int k = id - l * NC;
    float lam = (float)l * (1.0f / (GL - 1));
    float th = (k + 0.5f) * (PI_F / NC);
    float c  = C_MID + C_HALF * __cosf(th);

    float g0 = metric_eval(c,            lam, mW1, mb1, mW2, mb2, mW3, mb3);
    float gp = metric_eval(c + FD_EPS_F, lam, mW1, mb1, mW2, mb2, mW3, mb3);
    float gm = metric_eval(c - FD_EPS_F, lam, mW1, mb1, mW2, mb2, mW3, mb3);
    float dg = (gp - gm) * (1.0f / (2.0f * FD_EPS_F));
    g_nodes[id] = 0.5f * dg / g0;
}

__global__ void dct_kernel()
{
    int id = blockIdx.x * blockDim.x + threadIdx.x;
    if (id >= GL * NC) return;
    int l = id / NC;
    int j = id - l * NC;
    float s = 0.0f;
    for (int k = 0; k < NC; k++)
        s += g_nodes[l * NC + k] * __cosf((PI_F / NC) * (float)j * ((float)k + 0.5f));
    s *= (j == 0) ? (1.0f / NC) : (2.0f / NC);
    g_coef[l * NC + j] = s;
}

// ----------------------------- main kernel ---------------------------------

// Even/odd split Clenshaw: p(t) = sum a_j T_j(t)
//   even: sum a_{2k} T_k(u),  u = 2t^2-1   (standard Clenshaw)
//   odd:  t * sum a_{2k+1} V_k(u)          (V: 3rd-kind, V0=1, V1=2u-1,
//                                            V_k = 2u V_{k-1} - V_{k-2};
//                                            Clenshaw result = b0 - b1)
// Two independent chains -> half the dependent-FMA latency.
template<int NT>   // NT = total terms (even), NT/2 per chain
__device__ __forceinline__ u64 eval_gamma_eo(const u64 co[NC], u64 C)
{
    float cx, cy; upk(C, cx, cy);
    cx = fminf(fmaxf(cx, C_MIN), C_MAX);
    cy = fminf(fmaxf(cy, C_MIN), C_MAX);
    u64 T = pk(fmaf(cx, (float)C_INVH, (float)C_MOFF),
               fmaf(cy, (float)C_INVH, (float)C_MOFF));
    u64 U  = pfma(padd(T, T), T, PK_M1);     // u = 2t^2 - 1
    u64 U2 = padd(U, U);

    const int H = NT / 2;
    u64 be1 = 0ull, be2 = 0ull;   // even chain (T-basis over u)
    u64 bo1 = 0ull, bo2 = 0ull;   // odd chain  (V-basis over u)
#pragma unroll
    for (int k = H - 1; k >= 1; k--) {
        u64 de = pfma(be2, PK_M1, co[2 * k]);
        u64 be = pfma(U2, be1, de);
        be2 = be1; be1 = be;
        u64 dd = pfma(bo2, PK_M1, co[2 * k + 1]);
        u64 bo = pfma(U2, bo1, dd);
        bo2 = bo1; bo1 = bo;
    }
    u64 pe = pfma(U, be1, pfma(be2, PK_M1, co[0]));       // e0 - be2 + u*be1
    u64 b0 = pfma(U2, bo1, pfma(bo2, PK_M1, co[1]));      // o0 + 2u*bo1 - bo2
    u64 dv = pfma(bo1, PK_M1, b0);                        // b0 - bo1
    return pfma(T, dv, pe);
}

// 10 Euler steps, c/v only (shooting: truncated terms)
__device__ __forceinline__ u64 integrate_c(const u64 co[NC], u64 C0, u64 V0)
{
    u64 C = C0, V = V0;
#pragma unroll 1
    for (int s = 0; s < 10; s++) {
        u64 G   = eval_gamma_eo<NCS>(co, C);
        u64 Cn  = pfma(V, PK_DT, C);
        u64 gv  = pmul(G, V);
        u64 gvv = pmul(gv, V);
        V = pfma(gvv, PK_NDT, V);
        C = Cn;
    }
    return C;
}

// reference iterations 2..10 in closed form (affine model of F)
__device__ __forceinline__ float shoot_tail(float v0, float v1,
                                            float F0, float F1, float ctg)
{
    float dv = v1 - v0;
    float b  = __fdividef(F1 - F0, dv);
    float r  = 1.0f - 0.5f * b;
    float vs = v1 + __fdividef(ctg - F1, b);
    float r2 = r * r, r4 = r2 * r2, r8 = r4 * r4, r9 = r8 * r;
    float v10 = fmaf(r9, v1 - vs, vs);
    return (fabsf(dv) > 1e-6f) ? v10 : v1;
}

__global__ __launch_bounds__(256)
void geodesic_main_kernel(
    const float* __restrict__ c_src, const float* __restrict__ c_tgt,
    const float* __restrict__ lamv,  const float* __restrict__ A_src,
    const float* __restrict__ sW1,   const float* __restrict__ sb1,
    const float* __restrict__ sW2,   const float* __restrict__ sb2,
    float* __restrict__ out, int n)
{
    __shared__ u64  W1p[64];          // [j], [16+j], [48+j] used
    __shared__ u64  shW2[16];
    __shared__ float shC[16], shB1[16];
    __shared__ float shT2;

    const float KTH = 2.8853900817779268f;   // 2*log2(e)
    int t = threadIdx.x;
    if (t < 16) {
        int j = t;
        float a  = KTH * sW1[j];
        float b  = KTH * sW1[16 + j];
        float cw = KTH * sW1[32 + j];
        float dw = KTH * sW1[48 + j];
        W1p[j]      = pk(a, a);
        W1p[16 + j] = pk(b, b);
        W1p[48 + j] = pk(dw, dw);
        float w2 = sW2[j];
        shW2[j] = pk(-2.0f * w2, -2.0f * w2);
        shC[j]  = cw;
        shB1[j] = KTH * sb1[j];
    } else if (t == 16) {
        float s = sb2[0];
        for (int j = 0; j < 16; j++) s += sW2[j];
        shT2 = s;
    }
    __syncthreads();

    int half = (n + 1) >> 1;
    int i = blockIdx.x * 256 + t;
    if (i >= half) return;
    int i2 = i + half;
    bool has2 = (i2 < n);
    int j2 = has2 ? i2 : i;

    float c0x = c_src[i],  c0y = c_src[j2];
    float ctx = c_tgt[i],  cty = c_tgt[j2];
    float lmx = lamv[i],   lmy = lamv[j2];
    float a0x = A_src[i],  a0y = A_src[j2];

    // --- lambda-lerp of Chebyshev rows, packed ---
    float yx = fminf(fmaxf(lmx * (float)(GL - 1), 0.0f), (float)(GL - 1));
    float yy = fminf(fmaxf(lmy * (float)(GL - 1), 0.0f), (float)(GL - 1));
    int lx = min((int)yx, GL - 2);
    int ly = min((int)yy, GL - 2);
    float fx = yx - (float)lx;
    float fy = yy - (float)ly;

    const float4* rx0 = (const float4*)(g_coef + lx * NC);
    const float4* rx1 = (const float4*)(g_coef + (lx + 1) * NC);
    const float4* ry0 = (const float4*)(g_coef + ly * NC);
    const float4* ry1 = (const float4*)(g_coef + (ly + 1) * NC);

    u64 co[NC];
#pragma unroll
    for (int q = 0; q < NC / 4; q++) {
        float4 ax = __ldg(rx0 + q), bx = __ldg(rx1 + q);
        float4 ay = __ldg(ry0 + q), by = __ldg(ry1 + q);
        co[4*q+0] = pk(fmaf(fx, bx.x - ax.x, ax.x), fmaf(fy, by.x - ay.x, ay.x));
        co[4*q+1] = pk(fmaf(fx, bx.y - ax.y, ax.y), fmaf(fy, by.y - ay.y, ay.y));
        co[4*q+2] = pk(fmaf(fx, bx.z - ax.z, ax.z), fmaf(fy, by.z - ay.z, ay.z));
        co[4*q+3] = pk(fmaf(fx, bx.w - ax.w, ax.w), fmaf(fy, by.w - ay.w, ay.w));
    }

    // --- per-element static flow terms: S_j = k*(b1_j + lam*W1c_j) ---
    u64 S[16];
#pragma unroll
    for (int j = 0; j < 16; j++)
        S[j] = pk(fmaf(lmx, shC[j], shB1[j]), fmaf(lmy, shC[j], shB1[j]));

    // --- shooting: 2 truncated integrations + affine closed-form tail ---
    u64 C0p = pk(c0x, c0y);
    float v0x = ctx - c0x, v0y = cty - c0y;
    u64 F0p = integrate_c(co, C0p, pk(v0x, v0y));

    float F0x, F0y; upk(F0p, F0x, F0y);
    float v1x = fmaf(-0.5f, F0x - ctx, v0x);
    float v1y = fmaf(-0.5f, F0y - cty, v0y);
    u64 F1p = integrate_c(co, C0p, pk(v1x, v1y));
    float F1x, F1y; upk(F1p, F1x, F1y);

    float vx = shoot_tail(v0x, v1x, F0x, F1x, ctx);
    float vy = shoot_tail(v0y, v1y, F0y, F1y, cty);

    // --- final integrate with spectral flow (full NC terms) ---
    u64 C = C0p, V = pk(vx, vy), A = pk(a0x, a0y);
    u64 T2p = pk(shT2, shT2);
#pragma unroll 1
    for (int s = 0; s < 10; s++) {
        u64 G = eval_gamma_eo<NC>(co, C);
        u64 acc = T2p;
#pragma unroll
        for (int j = 0; j < 16; j += 2) {
            u64 pre0 = pfma(C, W1p[j], S[j]);
            pre0 = pfma(V, W1p[16 + j], pre0);
            pre0 = pfma(A, W1p[48 + j], pre0);
            float p0x, p0y; upk(pre0, p0x, p0y);
            u64 D0 = padd(pk(ex2f(p0x), ex2f(p0y)), PK_ONE);

            u64 pre1 = pfma(C, W1p[j + 1], S[j + 1]);
            pre1 = pfma(V, W1p[17 + j], pre1);
            pre1 = pfma(A, W1p[49 + j], pre1);
            float p1x, p1y; upk(pre1, p1x, p1y);
            u64 D1 = padd(pk(ex2f(p1x), ex2f(p1y)), PK_ONE);

            // one reciprocal per element serves both neurons: R = 1/(D0*D1)
            u64 P = pmul(D0, D1);
            float qx, qy; upk(P, qx, qy);
            u64 R  = pk(rcpf(qx), rcpf(qy));
            u64 r0 = pmul(R, D1);
            u64 r1 = pmul(R, D0);
            acc = pfma(r0, shW2[j],     acc);
            acc = pfma(r1, shW2[j + 1], acc);
        }
        u64 Cn  = pfma(V, PK_DT, C);
        u64 gv  = pmul(G, V);
        u64 gvv = pmul(gv, V);
        V = pfma(gvv, PK_NDT, V);
        A = pfma(acc, PK_DT, A);
        C = Cn;
    }

    float Ax, Ay; upk(A, Ax, Ay);
    out[i] = Ax;
    if (has2) out[i2] = Ay;
}

// ----------------------------- launcher ------------------------------------

extern "C" void kernel_launch(void* const* d_in, const int* in_sizes, int n_in,
                              void* d_out, int out_size)
{
    const float* c_src = (const float*)d_in[0];
    const float* c_tgt = (const float*)d_in[1];
    const float* lam   = (const float*)d_in[2];
    const float* A_src = (const float*)d_in[3];
    const float* mW1 = (const float*)d_in[4];
    const float* mb1 = (const float*)d_in[5];
    const float* mW2 = (const float*)d_in[6];
    const float* mb2 = (const float*)d_in[7];
    const float* mW3 = (const float*)d_in[8];
    const float* mb3 = (const float*)d_in[9];
    const float* sW1 = (const float*)d_in[10];
    const float* sb1 = (const float*)d_in[11];
    const float* sW2 = (const float*)d_in[12];
    const float* sb2 = (const float*)d_in[13];

    int n = in_sizes[0];
    const int TB = 256;

    int pre_blocks = (GL * NC + TB - 1) / TB;
    gamma_nodes_kernel<<<pre_blocks, TB>>>(mW1, mb1, mW2, mb2, mW3, mb3);
    dct_kernel<<<pre_blocks, TB>>>();

    int half = (n + 1) / 2;
    int blocks = (half + TB - 1) / TB;
    geodesic_main_kernel<<<blocks, TB>>>(c_src, c_tgt, lam, A_src,
                                         sW1, sb1, sW2, sb2,
                                         (float*)d_out, n);
}

// round 6
// speedup vs baseline: 2.1066x; 1.2206x over previous
#include <cuda_runtime.h>
#include <cuda_bf16.h>

// ---------------------------------------------------------------------------
// R6: R5 (260us) is FFMA2-slot bound (0.112us/slot), MUFU just under. Cuts:
//  1. SINGLE shooting integration: slope from drag model b = 2*T_eff - 1,
//     T_eff = (F0-c0)/v0 (error O((a v)^2) ~1e-3, tail sensitivity ~1e-5 in v).
//     Closed-form 10-iterate affine tail from v0 directly. Saves ~360 slots.
//  2. NC 16->12 (final), NCS 12->8 (shooting): Chebyshev decay rho~2.5 makes
//     a_12 ~ 6e-6 relative -- negligible.
//  3. Flow MLP unchanged (pairwise-batched rcp, ex2-based tanh).
//  Result: FMA pipe ~3640 cyc/warp vs MUFU 3840 -- balanced.
// ---------------------------------------------------------------------------

#define NC      12
#define NCS     8
#define GL      1024
#define C_MIN   (-1.0f)
#define C_MAX   (2.0f)
#define C_MID   (0.5f)
#define C_HALF  (1.5f)
#define C_INVH  (0.66666666666666667f)
#define C_MOFF  (-0.33333333333333333f)
#define PI_F    3.14159265358979323846f
#define FD_EPS_F 1e-4f

typedef unsigned long long u64;

__device__ float g_nodes[GL * NC];
__device__ float g_coef [GL * NC];

// packed f32x2 helpers ------------------------------------------------------
__device__ __forceinline__ u64 pk(float lo, float hi) {
    u64 r; asm("mov.b64 %0, {%1, %2};" : "=l"(r) : "f"(lo), "f"(hi)); return r;
}
__device__ __forceinline__ void upk(u64 a, float& x, float& y) {
    asm("mov.b64 {%0, %1}, %2;" : "=f"(x), "=f"(y) : "l"(a));
}
__device__ __forceinline__ u64 pfma(u64 a, u64 b, u64 c) {
    u64 d; asm("fma.rn.f32x2 %0, %1, %2, %3;" : "=l"(d) : "l"(a), "l"(b), "l"(c)); return d;
}
__device__ __forceinline__ u64 pmul(u64 a, u64 b) {
    u64 d; asm("mul.rn.f32x2 %0, %1, %2;" : "=l"(d) : "l"(a), "l"(b)); return d;
}
__device__ __forceinline__ u64 padd(u64 a, u64 b) {
    u64 d; asm("add.rn.f32x2 %0, %1, %2;" : "=l"(d) : "l"(a), "l"(b)); return d;
}
__device__ __forceinline__ float ex2f(float x) {
    float y; asm("ex2.approx.f32 %0, %1;" : "=f"(y) : "f"(x)); return y;
}
__device__ __forceinline__ float rcpf(float x) {
    float y; asm("rcp.approx.f32 %0, %1;" : "=f"(y) : "f"(x)); return y;
}

#define PK_M1   0xBF800000BF800000ULL   // (-1, -1)
#define PK_ONE  0x3F8000003F800000ULL   // ( 1,  1)
#define PK_DT   0x3DCCCCCD3DCCCCCDULL   // (0.1, 0.1)
#define PK_NDT  0xBDCCCCCDBDCCCCCDULL   // (-0.1, -0.1)

// ----------------------------- precompute ----------------------------------

__device__ __forceinline__ float metric_eval(
    float c, float lam,
    const float* __restrict__ mW1, const float* __restrict__ mb1,
    const float* __restrict__ mW2, const float* __restrict__ mb2,
    const float* __restrict__ mW3, const float* __restrict__ mb3)
{
    float h1[8];
#pragma unroll
    for (int j = 0; j < 8; j++)
        h1[j] = tanhf(fmaf(c, mW1[j], fmaf(lam, mW1[8 + j], mb1[j])));
    float h2[8];
#pragma unroll
    for (int j = 0; j < 8; j++) {
        float p = mb2[j];
#pragma unroll
        for (int k = 0; k < 8; k++) p = fmaf(h1[k], mW2[k * 8 + j], p);
        h2[j] = tanhf(p);
    }
    float o = mb3[0];
#pragma unroll
    for (int k = 0; k < 8; k++) o = fmaf(h2[k], mW3[k], o);
    float sp = (o > 20.0f) ? o : log1pf(expf(o));
    return sp + 1e-6f;
}

__global__ void gamma_nodes_kernel(
    const float* __restrict__ mW1, const float* __restrict__ mb1,
    const float* __restrict__ mW2, const float* __restrict__ mb2,
    const float* __restrict__ mW3, const float* __restrict__ mb3)
{
    int id = blockIdx.x * blockDim.x + threadIdx.x;
    if (id >= GL * NC) return;
    int l = id / NC;
    int k = id - l * NC;
    float lam = (float)l * (1.0f / (GL - 1));
    float th = (k + 0.5f) * (PI_F / NC);
    float c  = C_MID + C_HALF * __cosf(th);

    float g0 = metric_eval(c,            lam, mW1, mb1, mW2, mb2, mW3, mb3);
    float gp = metric_eval(c + FD_EPS_F, lam, mW1, mb1, mW2, mb2, mW3, mb3);
    float gm = metric_eval(c - FD_EPS_F, lam, mW1, mb1, mW2, mb2, mW3, mb3);
    float dg = (gp - gm) * (1.0f / (2.0f * FD_EPS_F));
    g_nodes[id] = 0.5f * dg / g0;
}

__global__ void dct_kernel()
{
    int id = blockIdx.x * blockDim.x + threadIdx.x;
    if (id >= GL * NC) return;
    int l = id / NC;
    int j = id - l * NC;
    float s = 0.0f;
    for (int k = 0; k < NC; k++)
        s += g_nodes[l * NC + k] * __cosf((PI_F / NC) * (float)j * ((float)k + 0.5f));
    s *= (j == 0) ? (1.0f / NC) : (2.0f / NC);
    g_coef[l * NC + j] = s;
}

// ----------------------------- main kernel ---------------------------------

// Even/odd split Clenshaw (two independent chains, half the dep latency).
template<int NT>
__device__ __forceinline__ u64 eval_gamma_eo(const u64 co[NC], u64 C)
{
    float cx, cy; upk(C, cx, cy);
    cx = fminf(fmaxf(cx, C_MIN), C_MAX);
    cy = fminf(fmaxf(cy, C_MIN), C_MAX);
    u64 T = pk(fmaf(cx, (float)C_INVH, (float)C_MOFF),
               fmaf(cy, (float)C_INVH, (float)C_MOFF));
    u64 U  = pfma(padd(T, T), T, PK_M1);     // u = 2t^2 - 1
    u64 U2 = padd(U, U);

    const int H = NT / 2;
    u64 be1 = 0ull, be2 = 0ull;   // even chain (T-basis over u)
    u64 bo1 = 0ull, bo2 = 0ull;   // odd chain  (V-basis over u)
#pragma unroll
    for (int k = H - 1; k >= 1; k--) {
        u64 de = pfma(be2, PK_M1, co[2 * k]);
        u64 be = pfma(U2, be1, de);
        be2 = be1; be1 = be;
        u64 dd = pfma(bo2, PK_M1, co[2 * k + 1]);
        u64 bo = pfma(U2, bo1, dd);
        bo2 = bo1; bo1 = bo;
    }
    u64 pe = pfma(U, be1, pfma(be2, PK_M1, co[0]));       // e0 - be2 + u*be1
    u64 b0 = pfma(U2, bo1, pfma(bo2, PK_M1, co[1]));      // o0 + 2u*bo1 - bo2
    u64 dv = pfma(bo1, PK_M1, b0);                        // b0 - bo1
    return pfma(T, dv, pe);
}

// 10 Euler steps, c/v only (shooting, truncated terms)
__device__ __forceinline__ u64 integrate_c(const u64 co[NC], u64 C0, u64 V0)
{
    u64 C = C0, V = V0;
#pragma unroll 1
    for (int s = 0; s < 10; s++) {
        u64 G   = eval_gamma_eo<NCS>(co, C);
        u64 Cn  = pfma(V, PK_DT, C);
        u64 gv  = pmul(G, V);
        u64 gvv = pmul(gv, V);
        V = pfma(gvv, PK_NDT, V);
        C = Cn;
    }
    return C;
}

// All 10 reference shooting iterations in closed form from ONE integration.
// F(v) = c0 + v*T_eff(v), T_eff ~ 1 - a*v  =>  dF/dv = 2*T_eff - 1.
__device__ __forceinline__ float shoot_single(float c0, float v0,
                                              float F0, float ctg)
{
    float Teff = __fdividef(F0 - c0, v0);
    float b    = 2.0f * Teff - 1.0f;
    bool ok    = (fabsf(v0) > 1e-7f) && (fabsf(b) > 0.1f);
    b = ok ? b : 1.0f;
    float vs = v0 + __fdividef(ctg - F0, b);
    float r  = 1.0f - 0.5f * b;
    float r2 = r * r, r4 = r2 * r2, r8 = r4 * r4, r10 = r8 * r2;
    return fmaf(r10, v0 - vs, vs);
}

__global__ __launch_bounds__(256)
void geodesic_main_kernel(
    const float* __restrict__ c_src, const float* __restrict__ c_tgt,
    const float* __restrict__ lamv,  const float* __restrict__ A_src,
    const float* __restrict__ sW1,   const float* __restrict__ sb1,
    const float* __restrict__ sW2,   const float* __restrict__ sb2,
    float* __restrict__ out, int n)
{
    __shared__ u64  W1p[64];          // [j], [16+j], [48+j] used
    __shared__ u64  shW2[16];
    __shared__ float shC[16], shB1[16];
    __shared__ float shT2;

    const float KTH = 2.8853900817779268f;   // 2*log2(e)
    int t = threadIdx.x;
    if (t < 16) {
        int j = t;
        float a  = KTH * sW1[j];
        float b  = KTH * sW1[16 + j];
        float cw = KTH * sW1[32 + j];
        float dw = KTH * sW1[48 + j];
        W1p[j]      = pk(a, a);
        W1p[16 + j] = pk(b, b);
        W1p[48 + j] = pk(dw, dw);
        float w2 = sW2[j];
        shW2[j] = pk(-2.0f * w2, -2.0f * w2);
        shC[j]  = cw;
        shB1[j] = KTH * sb1[j];
    } else if (t == 16) {
        float s = sb2[0];
        for (int j = 0; j < 16; j++) s += sW2[j];
        shT2 = s;
    }
    __syncthreads();

    int half = (n + 1) >> 1;
    int i = blockIdx.x * 256 + t;
    if (i >= half) return;
    int i2 = i + half;
    bool has2 = (i2 < n);
    int j2 = has2 ? i2 : i;

    float c0x = c_src[i],  c0y = c_src[j2];
    float ctx = c_tgt[i],  cty = c_tgt[j2];
    float lmx = lamv[i],   lmy = lamv[j2];
    float a0x = A_src[i],  a0y = A_src[j2];

    // --- lambda-lerp of Chebyshev rows, packed (NC=12: 3 float4 per row) ---
    float yx = fminf(fmaxf(lmx * (float)(GL - 1), 0.0f), (float)(GL - 1));
    float yy = fminf(fmaxf(lmy * (float)(GL - 1), 0.0f), (float)(GL - 1));
    int lx = min((int)yx, GL - 2);
    int ly = min((int)yy, GL - 2);
    float fx = yx - (float)lx;
    float fy = yy - (float)ly;

    const float4* rx0 = (const float4*)(g_coef + lx * NC);
    const float4* rx1 = (const float4*)(g_coef + (lx + 1) * NC);
    const float4* ry0 = (const float4*)(g_coef + ly * NC);
    const float4* ry1 = (const float4*)(g_coef + (ly + 1) * NC);

    u64 co[NC];
#pragma unroll
    for (int q = 0; q < NC / 4; q++) {
        float4 ax = __ldg(rx0 + q), bx = __ldg(rx1 + q);
        float4 ay = __ldg(ry0 + q), by = __ldg(ry1 + q);
        co[4*q+0] = pk(fmaf(fx, bx.x - ax.x, ax.x), fmaf(fy, by.x - ay.x, ay.x));
        co[4*q+1] = pk(fmaf(fx, bx.y - ax.y, ax.y), fmaf(fy, by.y - ay.y, ay.y));
        co[4*q+2] = pk(fmaf(fx, bx.z - ax.z, ax.z), fmaf(fy, by.z - ay.z, ay.z));
        co[4*q+3] = pk(fmaf(fx, bx.w - ax.w, ax.w), fmaf(fy, by.w - ay.w, ay.w));
    }

    // --- per-element static flow terms: S_j = k*(b1_j + lam*W1c_j) ---
    u64 S[16];
#pragma unroll
    for (int j = 0; j < 16; j++)
        S[j] = pk(fmaf(lmx, shC[j], shB1[j]), fmaf(lmy, shC[j], shB1[j]));

    // --- shooting: ONE truncated integration + derivative-model tail ---
    u64 C0p = pk(c0x, c0y);
    float v0x = ctx - c0x, v0y = cty - c0y;
    u64 F0p = integrate_c(co, C0p, pk(v0x, v0y));
    float F0x, F0y; upk(F0p, F0x, F0y);

    float vx = shoot_single(c0x, v0x, F0x, ctx);
    float vy = shoot_single(c0y, v0y, F0y, cty);

    // --- final integrate with spectral flow (full NC terms) ---
    u64 C = C0p, V = pk(vx, vy), A = pk(a0x, a0y);
    u64 T2p = pk(shT2, shT2);
#pragma unroll 1
    for (int s = 0; s < 10; s++) {
        u64 G = eval_gamma_eo<NC>(co, C);
        u64 acc = T2p;
#pragma unroll
        for (int j = 0; j < 16; j += 2) {
            u64 pre0 = pfma(C, W1p[j], S[j]);
            pre0 = pfma(V, W1p[16 + j], pre0);
            pre0 = pfma(A, W1p[48 + j], pre0);
            float p0x, p0y; upk(pre0, p0x, p0y);
            u64 D0 = padd(pk(ex2f(p0x), ex2f(p0y)), PK_ONE);

            u64 pre1 = pfma(C, W1p[j + 1], S[j + 1]);
            pre1 = pfma(V, W1p[17 + j], pre1);
            pre1 = pfma(A, W1p[49 + j], pre1);
            float p1x, p1y; upk(pre1, p1x, p1y);
            u64 D1 = padd(pk(ex2f(p1x), ex2f(p1y)), PK_ONE);

            // one reciprocal per element serves both neurons: R = 1/(D0*D1)
            u64 P = pmul(D0, D1);
            float qx, qy; upk(P, qx, qy);
            u64 R  = pk(rcpf(qx), rcpf(qy));
            u64 r0 = pmul(R, D1);
            u64 r1 = pmul(R, D0);
            acc = pfma(r0, shW2[j],     acc);
            acc = pfma(r1, shW2[j + 1], acc);
        }
        u64 Cn  = pfma(V, PK_DT, C);
        u64 gv  = pmul(G, V);
        u64 gvv = pmul(gv, V);
        V = pfma(gvv, PK_NDT, V);
        A = pfma(acc, PK_DT, A);
        C = Cn;
    }

    float Ax, Ay; upk(A, Ax, Ay);
    out[i] = Ax;
    if (has2) out[i2] = Ay;
}

// ----------------------------- launcher ------------------------------------

extern "C" void kernel_launch(void* const* d_in, const int* in_sizes, int n_in,
                              void* d_out, int out_size)
{
    const float* c_src = (const float*)d_in[0];
    const float* c_tgt = (const float*)d_in[1];
    const float* lam   = (const float*)d_in[2];
    const float* A_src = (const float*)d_in[3];
    const float* mW1 = (const float*)d_in[4];
    const float* mb1 = (const float*)d_in[5];
    const float* mW2 = (const float*)d_in[6];
    const float* mb2 = (const float*)d_in[7];
    const float* mW3 = (const float*)d_in[8];
    const float* mb3 = (const float*)d_in[9];
    const float* sW1 = (const float*)d_in[10];
    const float* sb1 = (const float*)d_in[11];
    const float* sW2 = (const float*)d_in[12];
    const float* sb2 = (const float*)d_in[13];

    int n = in_sizes[0];
    const int TB = 256;

    int pre_blocks = (GL * NC + TB - 1) / TB;
    gamma_nodes_kernel<<<pre_blocks, TB>>>(mW1, mb1, mW2, mb2, mW3, mb3);
    dct_kernel<<<pre_blocks, TB>>>();

    int half = (n + 1) / 2;
    int blocks = (half + TB - 1) / TB;
    geodesic_main_kernel<<<blocks, TB>>>(c_src, c_tgt, lam, A_src,
                                         sW1, sb1, sW2, sb2,
                                         (float*)d_out, n);
}